// round 12
// baseline (speedup 1.0000x reference)
#include <cuda_runtime.h>
#include <cuda_bf16.h>
#include <cstdint>
#include <math.h>

#define HH      256
#define G4      1024
#define BATCH   256
#define WIN     512
#define TT      519     // W + MAXLAG
#define MAXLAG  7
#define SREP    100
#define NDEC    25600   // BATCH * SREP
#define PSTEPS  24
#define ESTEPS  512
#define ENC_BLOCKS 128

// ---- encoder v4 smem layout (4-byte units) ----
#define WPK    132
#define MATSZ  (2 * 64 * WPK)
#define OFF_CHH (3 * MATSZ)
#define OFF_CHL (OFF_CHH + 1536)
#define OFF_RED (OFF_CHL + 1536)
#define OFF_SXW (OFF_RED + 32 * 68)
#define OFF_SXA (OFF_SXW + 64 * 8)
#define ENC_SMEM_UNITS (OFF_SXA + 32 * 8)
#define ENC_SMEM_BYTES (ENC_SMEM_UNITS * 4)

// ---- decoder dynamic smem layout (bytes) ----
#define DBM 128
#define DPK 12
#define DTILE   (DBM * DPK * 4)          // 6144 per tile
#define DO_AH   0                        // [2][128][12]
#define DO_AL   (2 * DTILE)
#define DO_BH   (4 * DTILE)
#define DO_BL   (6 * DTILE)
#define DO_RAWA (8 * DTILE)              // [2][128][16] float = 16384
#define DO_RAWB (DO_RAWA + 16384)
#define DO_BIAS (DO_RAWB + 16384)
#define DEC_SMEM_BYTES (DO_BIAS + 512)

// ---------------- scratch ----------------
__device__ __align__(128) float g_scaled[BATCH * TT];
__device__ float g_loc[BATCH];
__device__ float g_scale[BATCH];

__device__ __align__(128) float g_h0e[2][BATCH * HH];
__device__ __align__(128) float g_c0e[BATCH * HH];
__device__ __align__(128) float g_h1e[2][BATCH * HH];
__device__ __align__(128) float g_c1e[BATCH * HH];

__device__ __align__(128) float g_h0d[2][NDEC * HH];
__device__ __align__(128) float g_c0d[NDEC * HH];
__device__ __align__(128) float g_h1d[2][NDEC * HH];
__device__ __align__(128) float g_c1d[NDEC * HH];

__device__ __align__(128) float g_hist[NDEC * 32];

__device__ unsigned g_ectr = 0;

__device__ __forceinline__ float sigf(float x) { return 1.0f / (1.0f + expf(-x)); }

#define MMA_BF16(c, a, b) \
    asm volatile("mma.sync.aligned.m16n8k16.row.col.f32.bf16.bf16.f32 " \
                 "{%0,%1,%2,%3}, {%4,%5,%6,%7}, {%8,%9}, {%0,%1,%2,%3};\n" \
                 : "+f"((c)[0]), "+f"((c)[1]), "+f"((c)[2]), "+f"((c)[3]) \
                 : "r"((a)[0]), "r"((a)[1]), "r"((a)[2]), "r"((a)[3]), \
                   "r"((b)[0]), "r"((b)[1]))

__device__ __forceinline__ void bsplit2(float x, float y, unsigned& hi, unsigned& lo) {
    __nv_bfloat16 hx = __float2bfloat16(x);
    __nv_bfloat16 hy = __float2bfloat16(y);
    __nv_bfloat162 hp = __halves2bfloat162(hx, hy);
    __nv_bfloat162 lp = __halves2bfloat162(
        __float2bfloat16(x - __bfloat162float(hx)),
        __float2bfloat16(y - __bfloat162float(hy)));
    hi = *reinterpret_cast<unsigned*>(&hp);
    lo = *reinterpret_cast<unsigned*>(&lp);
}

__device__ __forceinline__ uint32_t smem_u32(const void* p) {
    uint32_t a;
    asm("{ .reg .u64 t; cvta.to.shared.u64 t, %1; cvt.u32.u64 %0, t; }" : "=r"(a) : "l"(p));
    return a;
}
__device__ __forceinline__ void cpa16(uint32_t dst, const void* src) {
    asm volatile("cp.async.ca.shared.global [%0], [%1], 16;" :: "r"(dst), "l"(src));
}
#define CP_COMMIT() asm volatile("cp.async.commit_group;" ::: "memory")
#define CP_WAIT1()  asm volatile("cp.async.wait_group 1;" ::: "memory")
#define CP_WAIT0()  asm volatile("cp.async.wait_group 0;" ::: "memory")

// ---------------- normalization ----------------
__global__ void norm_kernel(const float* __restrict__ tp) {
    int b = blockIdx.x;
    int tid = threadIdx.x;
    const float* row = tp + b * TT;

    double s = 0.0, q = 0.0;
    for (int j = tid; j < WIN; j += blockDim.x) {
        double v = (double)row[MAXLAG + j];
        s += v; q += v * v;
    }
    __shared__ double ss[256], sq[256];
    ss[tid] = s; sq[tid] = q;
    __syncthreads();
    for (int o = 128; o > 0; o >>= 1) {
        if (tid < o) { ss[tid] += ss[tid + o]; sq[tid] += sq[tid + o]; }
        __syncthreads();
    }
    __shared__ float smean, sscale;
    if (tid == 0) {
        double mean = ss[0] / (double)WIN;
        double var  = sq[0] / (double)WIN - mean * mean;
        if (var < 0.0) var = 0.0;
        float sd = (float)sqrt(var);
        float sc = (sd < 1e-10f) ? 1.0f : sd;
        smean = (float)mean; sscale = sc;
        g_loc[b] = (float)mean; g_scale[b] = sc;
    }
    __syncthreads();
    float m = smean, sc = sscale;
    for (int j = tid; j < TT; j += blockDim.x)
        g_scaled[b * TT + j] = (row[j] - m) / sc;
}

__global__ void zero_enc_kernel() {
    int i = blockIdx.x * blockDim.x + threadIdx.x;
    if (i < BATCH * HH) {
        g_h0e[0][i] = 0.f; g_c0e[i] = 0.f;
        g_h1e[0][i] = 0.f; g_c1e[i] = 0.f;
    }
    if (i == 0) g_ectr = 0;
}

// ---------------- persistent encoder v4 (unchanged from R9 win) ----------------
__global__ void __launch_bounds__(512) encoder_kernel(
    const float* __restrict__ w_ih0, const float* __restrict__ w_hh0,
    const float* __restrict__ b_ih0, const float* __restrict__ b_hh0,
    const float* __restrict__ w_ih1, const float* __restrict__ w_hh1,
    const float* __restrict__ b_ih1, const float* __restrict__ b_hh1)
{
    extern __shared__ unsigned esu[];
    float* esf = reinterpret_cast<float*>(esu);
    unsigned* W0h  = esu;                 unsigned* W0l  = esu + 64 * WPK;
    unsigned* WI1h = esu + MATSZ;         unsigned* WI1l = esu + MATSZ + 64 * WPK;
    unsigned* WH1h = esu + 2 * MATSZ;     unsigned* WH1l = esu + 2 * MATSZ + 64 * WPK;
    unsigned* CHH  = esu + OFF_CHH;
    unsigned* CHL  = esu + OFF_CHL;
    float* RED = esf + OFF_RED;
    float* SXW = esf + OFF_SXW;
    float* SXA = esf + OFF_SXA;

    const int t    = threadIdx.x;
    const int lane = t & 31;
    const int w    = t >> 5;
    const int grp  = w >> 3;
    const int wl   = w & 7;
    const int m_w  = (wl & 1) * 16;
    const int n_w  = (wl >> 1) * 16;
    const int qr   = lane >> 2;
    const int qc   = lane & 3;
    const int b0   = (blockIdx.x & 7) * 32;
    const int u0   = (blockIdx.x >> 3) * 16;

    for (int i = t; i < 64 * 128; i += 512) {
        int r  = i >> 7;
        int kp = i & 127;
        int grow = u0 + (r & 15) + ((r >> 4) << 8);
        unsigned hi, lo;
        bsplit2(w_hh0[grow * 256 + 2 * kp], w_hh0[grow * 256 + 2 * kp + 1], hi, lo);
        W0h[r * WPK + kp] = hi;  W0l[r * WPK + kp] = lo;
        bsplit2(w_ih1[grow * 256 + 2 * kp], w_ih1[grow * 256 + 2 * kp + 1], hi, lo);
        WI1h[r * WPK + kp] = hi; WI1l[r * WPK + kp] = lo;
        bsplit2(w_hh1[grow * 256 + 2 * kp], w_hh1[grow * 256 + 2 * kp + 1], hi, lo);
        WH1h[r * WPK + kp] = hi; WH1l[r * WPK + kp] = lo;
    }
    if (t < 64) {
        int grow = u0 + (t & 15) + ((t >> 4) << 8);
#pragma unroll
        for (int k = 0; k < 7; k++) SXW[t * 8 + k] = w_ih0[grow * 7 + k];
    }

    const int eul = t & 15;
    const int er  = t >> 4;
    float bI0 = 0, bF0 = 0, bG0 = 0, bO0 = 0, bI1 = 0, bF1 = 0, bG1 = 0, bO1 = 0;
    if (t < 256) {
        int u = u0 + eul;
        bI0 = b_ih0[u]       + b_hh0[u];
        bF0 = b_ih0[u + 256] + b_hh0[u + 256];
        bG0 = b_ih0[u + 512] + b_hh0[u + 512];
        bO0 = b_ih0[u + 768] + b_hh0[u + 768];
        bI1 = b_ih1[u]       + b_hh1[u];
        bF1 = b_ih1[u + 256] + b_hh1[u + 256];
        bG1 = b_ih1[u + 512] + b_hh1[u + 512];
        bO1 = b_ih1[u + 768] + b_hh1[u + 768];
    }
    __syncthreads();

    const int gt   = t & 255;
    const int prow = gt >> 3;
    const int pc   = gt & 7;
    unsigned* CHHg = CHH + grp * 768;
    unsigned* CHLg = CHL + grp * 768;

    auto gemm_tc = [&](const float* act, const unsigned* Wh, const unsigned* Wl,
                       float (&acc)[2][4]) {
        const int kb  = grp * 128;
        const int kpb = grp * 64;
        {
            float2 p = __ldcg((const float2*)(act + (b0 + prow) * HH + kb + pc * 2));
            unsigned hi, lo; bsplit2(p.x, p.y, hi, lo);
            CHHg[prow * 12 + pc] = hi;
            CHLg[prow * 12 + pc] = lo;
        }
        __syncthreads();
        for (int ch = 0; ch < 8; ch++) {
            float2 nxt;
            const bool have = (ch + 1) < 8;
            if (have)
                nxt = __ldcg((const float2*)(act + (b0 + prow) * HH + kb + (ch + 1) * 16 + pc * 2));
            const unsigned* hbh = CHHg + (ch & 1) * 384;
            const unsigned* hbl = CHLg + (ch & 1) * 384;
            unsigned ahi[4], alo[4];
            ahi[0] = hbh[(m_w + qr) * 12 + qc];
            ahi[1] = hbh[(m_w + qr + 8) * 12 + qc];
            ahi[2] = hbh[(m_w + qr) * 12 + qc + 4];
            ahi[3] = hbh[(m_w + qr + 8) * 12 + qc + 4];
            alo[0] = hbl[(m_w + qr) * 12 + qc];
            alo[1] = hbl[(m_w + qr + 8) * 12 + qc];
            alo[2] = hbl[(m_w + qr) * 12 + qc + 4];
            alo[3] = hbl[(m_w + qr + 8) * 12 + qc + 4];
#pragma unroll
            for (int f = 0; f < 2; f++) {
                int wr  = (n_w + f * 8 + qr) * WPK + kpb + ch * 8;
                unsigned bhi[2] = {Wh[wr + qc], Wh[wr + qc + 4]};
                unsigned blo[2] = {Wl[wr + qc], Wl[wr + qc + 4]};
                MMA_BF16(acc[f], ahi, bhi);
                MMA_BF16(acc[f], ahi, blo);
                MMA_BF16(acc[f], alo, bhi);
            }
            if (have) {
                unsigned hi, lo; bsplit2(nxt.x, nxt.y, hi, lo);
                CHHg[((ch + 1) & 1) * 384 + prow * 12 + pc] = hi;
                CHLg[((ch + 1) & 1) * 384 + prow * 12 + pc] = lo;
            }
            __syncthreads();
        }
    };

    auto reduce_store = [&](float (&acc)[2][4]) {
        if (grp == 1) {
#pragma unroll
            for (int f = 0; f < 2; f++)
#pragma unroll
                for (int half = 0; half < 2; half++)
#pragma unroll
                    for (int j = 0; j < 2; j++)
                        RED[(m_w + qr + half * 8) * 68 + n_w + f * 8 + 2 * qc + j] =
                            acc[f][half * 2 + j];
        }
        __syncthreads();
        if (grp == 0) {
#pragma unroll
            for (int f = 0; f < 2; f++)
#pragma unroll
                for (int half = 0; half < 2; half++)
#pragma unroll
                    for (int j = 0; j < 2; j++)
                        RED[(m_w + qr + half * 8) * 68 + n_w + f * 8 + 2 * qc + j] +=
                            acc[f][half * 2 + j];
        }
        __syncthreads();
    };

    for (int step = 0; step < ESTEPS; step++) {
        const int pa = step & 1, pb = pa ^ 1;
        float* h0b = g_h0e[pb];
        float* h1b = g_h1e[pb];

        if (t < 32) {
            const float* xr = g_scaled + (b0 + t) * TT + step + 6;
#pragma unroll
            for (int k = 0; k < 7; k++) SXA[t * 8 + k] = xr[-k];
        }

        float acc[2][4];
#pragma unroll
        for (int f = 0; f < 2; f++)
#pragma unroll
            for (int r = 0; r < 4; r++) acc[f][r] = 0.f;

        gemm_tc(g_h0e[pa], W0h, W0l, acc);
        reduce_store(acc);

        if (t < 256) {
#pragma unroll
            for (int h2 = 0; h2 < 2; h2++) {
                int r = er + 16 * h2;
                float gi = RED[r * 68 + eul]      + bI0;
                float gf = RED[r * 68 + 16 + eul] + bF0;
                float gg = RED[r * 68 + 32 + eul] + bG0;
                float go = RED[r * 68 + 48 + eul] + bO0;
#pragma unroll
                for (int k = 0; k < 7; k++) {
                    float x = SXA[r * 8 + k];
                    gi = fmaf(x, SXW[eul * 8 + k], gi);
                    gf = fmaf(x, SXW[(16 + eul) * 8 + k], gf);
                    gg = fmaf(x, SXW[(32 + eul) * 8 + k], gg);
                    go = fmaf(x, SXW[(48 + eul) * 8 + k], go);
                }
                int idx = (b0 + r) * HH + (u0 + eul);
                float c = g_c0e[idx];
                float cn = sigf(gf) * c + sigf(gi) * tanhf(gg);
                g_c0e[idx] = cn;
                h0b[idx] = sigf(go) * tanhf(cn);
            }
        }
        __syncthreads();
        if (t == 0) { __threadfence(); atomicAdd(&g_ectr, 1u); }

#pragma unroll
        for (int f = 0; f < 2; f++)
#pragma unroll
            for (int r = 0; r < 4; r++) acc[f][r] = 0.f;

        if (t == 0) {
            unsigned tgt = 256u * (unsigned)step;
            while (*(volatile unsigned*)&g_ectr < tgt) { }
        }
        __syncthreads();
        gemm_tc(g_h1e[pa], WH1h, WH1l, acc);

        if (t == 0) {
            unsigned tgt = 256u * (unsigned)step + 128u;
            while (*(volatile unsigned*)&g_ectr < tgt) { }
        }
        __syncthreads();
        gemm_tc(h0b, WI1h, WI1l, acc);

        reduce_store(acc);

        if (t < 256) {
#pragma unroll
            for (int h2 = 0; h2 < 2; h2++) {
                int r = er + 16 * h2;
                float gi = RED[r * 68 + eul]      + bI1;
                float gf = RED[r * 68 + 16 + eul] + bF1;
                float gg = RED[r * 68 + 32 + eul] + bG1;
                float go = RED[r * 68 + 48 + eul] + bO1;
                int idx = (b0 + r) * HH + (u0 + eul);
                float c = g_c1e[idx];
                float cn = sigf(gf) * c + sigf(gi) * tanhf(gg);
                g_c1e[idx] = cn;
                h1b[idx] = sigf(go) * tanhf(cn);
            }
        }
        __syncthreads();
        if (t == 0) { __threadfence(); atomicAdd(&g_ectr, 1u); }
    }
}

// ---------------- decoder cell v5: R6 numerics + cp.async double-buffered staging ----------------
__global__ void __launch_bounds__(256, 2) dec_cell_bf16(
    const float* __restrict__ xs,        // lag base (g_hist + p + 6) or null
    const float* __restrict__ w_ihs,     // (1024,7)
    const float* __restrict__ xb,        // big x (N,256) or null
    const float* __restrict__ w_ihb,     // (1024,256)
    const float* __restrict__ h_in,      // (N,256)
    const float* __restrict__ w_hh,      // (1024,256)
    const float* __restrict__ b_ih, const float* __restrict__ b_hh,
    const float* __restrict__ c_in,
    float* __restrict__ h_out, float* __restrict__ c_out)
{
    extern __shared__ __align__(128) char dsm[];
    unsigned* tAhi = (unsigned*)(dsm + DO_AH);    // [2][128][12]
    unsigned* tAlo = (unsigned*)(dsm + DO_AL);
    unsigned* tBhi = (unsigned*)(dsm + DO_BH);
    unsigned* tBlo = (unsigned*)(dsm + DO_BL);
    float* rawA = (float*)(dsm + DO_RAWA);        // [2][128][16]
    float* rawB = (float*)(dsm + DO_RAWB);
    float* sBias = (float*)(dsm + DO_BIAS);

    const int t    = threadIdx.x;
    const int lane = t & 31;
    const int wid  = t >> 5;
    const int m0w  = (wid & 1) * 64;
    const int u0w  = (wid >> 1) * 8;
    const int b0   = blockIdx.x * DBM;
    const int u0   = blockIdx.y * 32;

    const int lrow = t >> 1;             // 0..127
    const int lc0  = (t & 1) * 8;        // float col base (0 or 8)
    const int lp0  = (t & 1) * 4;        // packed col base (0 or 4)
    const int lgrow = u0 + (lrow & 31) + ((lrow >> 5) << 8);

    if (t < 128) {
        int grow = u0 + (t & 31) + ((t >> 5) << 8);
        sBias[t] = b_ih[grow] + b_hh[grow];
    }

    float acc[4][4][4];
#pragma unroll
    for (int mi = 0; mi < 4; mi++)
#pragma unroll
        for (int g = 0; g < 4; g++)
#pragma unroll
            for (int r = 0; r < 4; r++) acc[mi][g][r] = 0.f;

    const int qr = lane >> 2;
    const int qc = lane & 3;

    auto compute_chunk = [&](int buf) {
        const unsigned* AH = tAhi + buf * (DBM * DPK);
        const unsigned* AL = tAlo + buf * (DBM * DPK);
        const unsigned* BH = tBhi + buf * (DBM * DPK);
        const unsigned* BL = tBlo + buf * (DBM * DPK);
        unsigned ahi[4][4], alo[4][4];
#pragma unroll
        for (int mi = 0; mi < 4; mi++) {
            int r = m0w + mi * 16 + qr;
            ahi[mi][0] = AH[r * DPK + qc];           ahi[mi][1] = AH[(r + 8) * DPK + qc];
            ahi[mi][2] = AH[r * DPK + qc + 4];       ahi[mi][3] = AH[(r + 8) * DPK + qc + 4];
            alo[mi][0] = AL[r * DPK + qc];           alo[mi][1] = AL[(r + 8) * DPK + qc];
            alo[mi][2] = AL[r * DPK + qc + 4];       alo[mi][3] = AL[(r + 8) * DPK + qc + 4];
        }
        unsigned bhi[4][2], blo[4][2];
#pragma unroll
        for (int g = 0; g < 4; g++) {
            int br = g * 32 + u0w + qr;
            bhi[g][0] = BH[br * DPK + qc]; bhi[g][1] = BH[br * DPK + qc + 4];
            blo[g][0] = BL[br * DPK + qc]; blo[g][1] = BL[br * DPK + qc + 4];
        }
#pragma unroll
        for (int mi = 0; mi < 4; mi++)
#pragma unroll
            for (int g = 0; g < 4; g++) {
                MMA_BF16(acc[mi][g], ahi[mi], bhi[g]);
                MMA_BF16(acc[mi][g], ahi[mi], blo[g]);
                MMA_BF16(acc[mi][g], alo[mi], bhi[g]);
            }
    };

    auto store_a8 = [&](int buf, const float* v) {
        unsigned hi[4], lo[4];
#pragma unroll
        for (int j = 0; j < 4; j++) bsplit2(v[2 * j], v[2 * j + 1], hi[j], lo[j]);
        *(uint4*)(tAhi + buf * (DBM * DPK) + lrow * DPK + lp0) = make_uint4(hi[0], hi[1], hi[2], hi[3]);
        *(uint4*)(tAlo + buf * (DBM * DPK) + lrow * DPK + lp0) = make_uint4(lo[0], lo[1], lo[2], lo[3]);
    };
    auto store_b8 = [&](int buf, const float* v) {
        unsigned hi[4], lo[4];
#pragma unroll
        for (int j = 0; j < 4; j++) bsplit2(v[2 * j], v[2 * j + 1], hi[j], lo[j]);
        *(uint4*)(tBhi + buf * (DBM * DPK) + lrow * DPK + lp0) = make_uint4(hi[0], hi[1], hi[2], hi[3]);
        *(uint4*)(tBlo + buf * (DBM * DPK) + lrow * DPK + lp0) = make_uint4(lo[0], lo[1], lo[2], lo[3]);
    };

    int tb = 0;  // tile buffer parity

    // -------- lag chunk (K=7 zero-padded to 16) --------
    if (xs != nullptr) {
        float va[8], vb[8];
#pragma unroll
        for (int cc = 0; cc < 8; cc++) {
            int k = lc0 + cc;
            va[cc] = (k < 7) ? xs[(b0 + lrow) * 32 - k] : 0.f;
            vb[cc] = (k < 7) ? w_ihs[lgrow * 7 + k] : 0.f;
        }
        store_a8(tb, va);
        store_b8(tb, vb);
        __syncthreads();
        compute_chunk(tb);
        tb ^= 1;
    }

    // -------- dense K=256 segments, cp.async double-buffered --------
    const uint32_t aslot = smem_u32(rawA) + (lrow * 16 + lc0) * 4;
    const uint32_t bslot = smem_u32(rawB) + (lrow * 16 + lc0) * 4;

    auto gemm_segment = [&](const float* __restrict__ act, const float* __restrict__ wgt) {
        const float* asrc = act + (long long)(b0 + lrow) * HH + lc0;
        const float* wsrc = wgt + (long long)lgrow * HH + lc0;
        // prologue: chunk 0 into raw buf 0
        cpa16(aslot, asrc); cpa16(aslot + 16, asrc + 4);
        cpa16(bslot, wsrc); cpa16(bslot + 16, wsrc + 4);
        CP_COMMIT();
        for (int ch = 0; ch < 16; ch++) {
            const int rcur = ch & 1, rnxt = rcur ^ 1;
            if (ch + 1 < 16) {
                const float* a2 = asrc + (ch + 1) * 16;
                const float* w2 = wsrc + (ch + 1) * 16;
                uint32_t an = aslot + rnxt * 8192;
                uint32_t bn = bslot + rnxt * 8192;
                cpa16(an, a2); cpa16(an + 16, a2 + 4);
                cpa16(bn, w2); cpa16(bn + 16, w2 + 4);
                CP_COMMIT();
                CP_WAIT1();      // own chunk-ch group complete
            } else {
                CP_WAIT0();
            }
            // split own staged bytes (no cross-thread raw dependency)
            const float* ra = rawA + rcur * 2048 + lrow * 16 + lc0;
            const float* rb = rawB + rcur * 2048 + lrow * 16 + lc0;
            float av[8], wv[8];
            *(float4*)(av)     = *(const float4*)(ra);
            *(float4*)(av + 4) = *(const float4*)(ra + 4);
            *(float4*)(wv)     = *(const float4*)(rb);
            *(float4*)(wv + 4) = *(const float4*)(rb + 4);
            store_a8(tb, av);
            store_b8(tb, wv);
            __syncthreads();
            compute_chunk(tb);
            tb ^= 1;
        }
    };

    if (xb != nullptr) gemm_segment(xb, w_ihb);
    gemm_segment(h_in, w_hh);

    // -------- epilogue: fused LSTM nonlinearity --------
#pragma unroll
    for (int mi = 0; mi < 4; mi++) {
        int rbase = b0 + m0w + mi * 16 + qr;
#pragma unroll
        for (int half = 0; half < 2; half++) {
            int row = rbase + half * 8;
#pragma unroll
            for (int j = 0; j < 2; j++) {
                int ucol = 2 * qc + j;
                int u = u0 + u0w + ucol;
                int ci = half * 2 + j;
                float gi_ = acc[mi][0][ci] + sBias[ 0 + u0w + ucol];
                float gf  = acc[mi][1][ci] + sBias[32 + u0w + ucol];
                float gg  = acc[mi][2][ci] + sBias[64 + u0w + ucol];
                float go  = acc[mi][3][ci] + sBias[96 + u0w + ucol];
                long long idx = (long long)row * HH + u;
                float c = c_in[idx];
                float cn = sigf(gf) * c + sigf(gi_) * tanhf(gg);
                float hn = sigf(go) * tanhf(cn);
                c_out[idx] = cn;
                h_out[idx] = hn;
            }
        }
    }
}

// ---------------- replicate encoder state x100 + init history ----------------
__global__ void replicate_kernel() {
    int row = blockIdx.x;
    int u   = threadIdx.x;
    int b   = row / SREP;
    long long d = (long long)row * HH + u;
    long long s = (long long)b * HH + u;
    g_h0d[0][d] = g_h0e[0][s];
    g_c0d[d]    = g_c0e[s];
    g_h1d[0][d] = g_h1e[0][s];
    g_c1d[d]    = g_c1e[s];
    if (u < MAXLAG) g_hist[row * 32 + u] = g_scaled[b * TT + WIN + u];
}

// ---------------- mu/sigma head + sampling ----------------
__global__ void head_kernel(const float* __restrict__ h1,
                            const float* __restrict__ w_mu, const float* __restrict__ b_mu,
                            const float* __restrict__ w_sig, const float* __restrict__ b_sig,
                            const float* __restrict__ eps_p, int p) {
    int gid  = blockIdx.x * blockDim.x + threadIdx.x;
    int warp = gid >> 5;
    int lane = gid & 31;
    if (warp >= NDEC) return;
    const float* hr = h1 + (long long)warp * HH;
    float mu = 0.f, sg = 0.f;
#pragma unroll
    for (int k = lane; k < HH; k += 32) {
        float h = hr[k];
        mu = fmaf(h, w_mu[k], mu);
        sg = fmaf(h, w_sig[k], sg);
    }
#pragma unroll
    for (int o = 16; o > 0; o >>= 1) {
        mu += __shfl_xor_sync(0xffffffffu, mu, o);
        sg += __shfl_xor_sync(0xffffffffu, sg, o);
    }
    if (lane == 0) {
        mu += b_mu[0];
        sg += b_sig[0];
        float sp = (sg > 20.f) ? sg : log1pf(expf(sg));
        float sample = mu + sp * eps_p[warp];
        g_hist[warp * 32 + MAXLAG + p] = sample;
    }
}

// ---------------- mean over samples + denormalize ----------------
__global__ void reduce_kernel(float* __restrict__ out) {
    int gid  = blockIdx.x * blockDim.x + threadIdx.x;
    int warp = gid >> 5;
    int lane = gid & 31;
    if (warp >= BATCH * PSTEPS) return;
    int b = warp / PSTEPS;
    int p = warp % PSTEPS;
    float s = 0.f;
    for (int ss = lane; ss < SREP; ss += 32)
        s += g_hist[(b * SREP + ss) * 32 + MAXLAG + p];
#pragma unroll
    for (int o = 16; o > 0; o >>= 1) s += __shfl_xor_sync(0xffffffffu, s, o);
    if (lane == 0)
        out[b * PSTEPS + p] = s * (1.0f / (float)SREP) * g_scale[b] + g_loc[b];
}

// ---------------- launch ----------------
extern "C" void kernel_launch(void* const* d_in, const int* in_sizes, int n_in,
                              void* d_out, int out_size) {
    const float* targets = (const float*)d_in[0];
    const float* w_ih0   = (const float*)d_in[1];
    const float* w_hh0   = (const float*)d_in[2];
    const float* b_ih0   = (const float*)d_in[3];
    const float* b_hh0   = (const float*)d_in[4];
    const float* w_ih1   = (const float*)d_in[5];
    const float* w_hh1   = (const float*)d_in[6];
    const float* b_ih1   = (const float*)d_in[7];
    const float* b_hh1   = (const float*)d_in[8];
    const float* w_mu    = (const float*)d_in[9];
    const float* b_mu    = (const float*)d_in[10];
    const float* w_sigma = (const float*)d_in[11];
    const float* b_sigma = (const float*)d_in[12];
    const float* eps     = (const float*)d_in[13];
    float* out = (float*)d_out;

    float *h0d, *c0d, *h1d, *c1d, *hist;
    cudaGetSymbolAddress((void**)&h0d, g_h0d);
    cudaGetSymbolAddress((void**)&c0d, g_c0d);
    cudaGetSymbolAddress((void**)&h1d, g_h1d);
    cudaGetSymbolAddress((void**)&c1d, g_c1d);
    cudaGetSymbolAddress((void**)&hist, g_hist);

    cudaFuncSetAttribute(encoder_kernel,
                         cudaFuncAttributeMaxDynamicSharedMemorySize, ENC_SMEM_BYTES);
    cudaFuncSetAttribute(dec_cell_bf16,
                         cudaFuncAttributeMaxDynamicSharedMemorySize, DEC_SMEM_BYTES);

    norm_kernel<<<BATCH, 256>>>(targets);
    zero_enc_kernel<<<(BATCH * HH + 255) / 256, 256>>>();

    encoder_kernel<<<ENC_BLOCKS, 512, ENC_SMEM_BYTES>>>(
        w_ih0, w_hh0, b_ih0, b_hh0, w_ih1, w_hh1, b_ih1, b_hh1);

    replicate_kernel<<<NDEC, 256>>>();

    for (int p = 0; p < PSTEPS; p++) {
        int pa = p & 1, pb = pa ^ 1;
        dec_cell_bf16<<<dim3(NDEC / DBM, 8), 256, DEC_SMEM_BYTES>>>(
            hist + p + 6, w_ih0,
            nullptr, nullptr,
            h0d + pa * (NDEC * HH), w_hh0, b_ih0, b_hh0,
            c0d, h0d + pb * (NDEC * HH), c0d);
        dec_cell_bf16<<<dim3(NDEC / DBM, 8), 256, DEC_SMEM_BYTES>>>(
            nullptr, nullptr,
            h0d + pb * (NDEC * HH), w_ih1,
            h1d + pa * (NDEC * HH), w_hh1, b_ih1, b_hh1,
            c1d, h1d + pb * (NDEC * HH), c1d);
        head_kernel<<<(NDEC * 32 + 255) / 256, 256>>>(
            h1d + pb * (NDEC * HH), w_mu, b_mu, w_sigma, b_sigma,
            eps + (long long)p * NDEC, p);
    }

    reduce_kernel<<<(BATCH * PSTEPS * 32 + 255) / 256, 256>>>(out);
}

// round 13
// speedup vs baseline: 1.0933x; 1.0933x over previous
#include <cuda_runtime.h>
#include <cuda_bf16.h>
#include <cstdint>
#include <math.h>

#define HH      256
#define G4      1024
#define BATCH   256
#define WIN     512
#define TT      519     // W + MAXLAG
#define MAXLAG  7
#define SREP    100
#define NDEC    25600   // BATCH * SREP
#define PSTEPS  24
#define ESTEPS  512
#define ENC_BLOCKS 128

// ---- encoder v4 smem layout (4-byte units) ----
#define WPK    132
#define MATSZ  (2 * 64 * WPK)
#define OFF_CHH (3 * MATSZ)
#define OFF_CHL (OFF_CHH + 1536)
#define OFF_RED (OFF_CHL + 1536)
#define OFF_SXW (OFF_RED + 32 * 68)
#define OFF_SXA (OFF_SXW + 64 * 8)
#define ENC_SMEM_UNITS (OFF_SXA + 32 * 8)
#define ENC_SMEM_BYTES (ENC_SMEM_UNITS * 4)

// ---- decoder dynamic smem (bytes): 2-buffer mma tiles + bias ----
#define DBM 128
#define DPK 12
#define DTILEU (DBM * DPK)               // units per tile buffer (1536)
#define DO_AH  0
#define DO_AL  (2 * DTILEU * 4)
#define DO_BH  (4 * DTILEU * 4)
#define DO_BL  (6 * DTILEU * 4)
#define DO_BIAS (8 * DTILEU * 4)
#define DEC_SMEM_BYTES (DO_BIAS + 512)

// ---------------- scratch ----------------
__device__ __align__(128) float g_scaled[BATCH * TT];
__device__ float g_loc[BATCH];
__device__ float g_scale[BATCH];

__device__ __align__(128) float g_h0e[2][BATCH * HH];
__device__ __align__(128) float g_c0e[BATCH * HH];
__device__ __align__(128) float g_h1e[2][BATCH * HH];
__device__ __align__(128) float g_c1e[BATCH * HH];

__device__ __align__(128) float g_h0d[2][NDEC * HH];
__device__ __align__(128) float g_c0d[NDEC * HH];
__device__ __align__(128) float g_h1d[2][NDEC * HH];
__device__ __align__(128) float g_c1d[NDEC * HH];

__device__ __align__(128) float g_hist[NDEC * 32];
__device__ __align__(128) float g_musig[PSTEPS * NDEC * 2];

__device__ unsigned g_ectr = 0;

__device__ __forceinline__ float sigf(float x) { return 1.0f / (1.0f + expf(-x)); }

#define MMA_BF16(c, a, b) \
    asm volatile("mma.sync.aligned.m16n8k16.row.col.f32.bf16.bf16.f32 " \
                 "{%0,%1,%2,%3}, {%4,%5,%6,%7}, {%8,%9}, {%0,%1,%2,%3};\n" \
                 : "+f"((c)[0]), "+f"((c)[1]), "+f"((c)[2]), "+f"((c)[3]) \
                 : "r"((a)[0]), "r"((a)[1]), "r"((a)[2]), "r"((a)[3]), \
                   "r"((b)[0]), "r"((b)[1]))

__device__ __forceinline__ void bsplit2(float x, float y, unsigned& hi, unsigned& lo) {
    __nv_bfloat16 hx = __float2bfloat16(x);
    __nv_bfloat16 hy = __float2bfloat16(y);
    __nv_bfloat162 hp = __halves2bfloat162(hx, hy);
    __nv_bfloat162 lp = __halves2bfloat162(
        __float2bfloat16(x - __bfloat162float(hx)),
        __float2bfloat16(y - __bfloat162float(hy)));
    hi = *reinterpret_cast<unsigned*>(&hp);
    lo = *reinterpret_cast<unsigned*>(&lp);
}

// ---------------- normalization ----------------
__global__ void norm_kernel(const float* __restrict__ tp) {
    int b = blockIdx.x;
    int tid = threadIdx.x;
    const float* row = tp + b * TT;

    double s = 0.0, q = 0.0;
    for (int j = tid; j < WIN; j += blockDim.x) {
        double v = (double)row[MAXLAG + j];
        s += v; q += v * v;
    }
    __shared__ double ss[256], sq[256];
    ss[tid] = s; sq[tid] = q;
    __syncthreads();
    for (int o = 128; o > 0; o >>= 1) {
        if (tid < o) { ss[tid] += ss[tid + o]; sq[tid] += sq[tid + o]; }
        __syncthreads();
    }
    __shared__ float smean, sscale;
    if (tid == 0) {
        double mean = ss[0] / (double)WIN;
        double var  = sq[0] / (double)WIN - mean * mean;
        if (var < 0.0) var = 0.0;
        float sd = (float)sqrt(var);
        float sc = (sd < 1e-10f) ? 1.0f : sd;
        smean = (float)mean; sscale = sc;
        g_loc[b] = (float)mean; g_scale[b] = sc;
    }
    __syncthreads();
    float m = smean, sc = sscale;
    for (int j = tid; j < TT; j += blockDim.x)
        g_scaled[b * TT + j] = (row[j] - m) / sc;
}

__global__ void zero_enc_kernel() {
    int i = blockIdx.x * blockDim.x + threadIdx.x;
    if (i < BATCH * HH) {
        g_h0e[0][i] = 0.f; g_c0e[i] = 0.f;
        g_h1e[0][i] = 0.f; g_c1e[i] = 0.f;
    }
    if (i == 0) g_ectr = 0;
}

__global__ void zero_musig_kernel() {
    int i = blockIdx.x * blockDim.x + threadIdx.x;
    int n = PSTEPS * NDEC * 2;
    for (; i < n; i += gridDim.x * blockDim.x) g_musig[i] = 0.f;
}

// ---------------- persistent encoder v4 (unchanged from R9 win) ----------------
__global__ void __launch_bounds__(512) encoder_kernel(
    const float* __restrict__ w_ih0, const float* __restrict__ w_hh0,
    const float* __restrict__ b_ih0, const float* __restrict__ b_hh0,
    const float* __restrict__ w_ih1, const float* __restrict__ w_hh1,
    const float* __restrict__ b_ih1, const float* __restrict__ b_hh1)
{
    extern __shared__ unsigned esu[];
    float* esf = reinterpret_cast<float*>(esu);
    unsigned* W0h  = esu;                 unsigned* W0l  = esu + 64 * WPK;
    unsigned* WI1h = esu + MATSZ;         unsigned* WI1l = esu + MATSZ + 64 * WPK;
    unsigned* WH1h = esu + 2 * MATSZ;     unsigned* WH1l = esu + 2 * MATSZ + 64 * WPK;
    unsigned* CHH  = esu + OFF_CHH;
    unsigned* CHL  = esu + OFF_CHL;
    float* RED = esf + OFF_RED;
    float* SXW = esf + OFF_SXW;
    float* SXA = esf + OFF_SXA;

    const int t    = threadIdx.x;
    const int lane = t & 31;
    const int w    = t >> 5;
    const int grp  = w >> 3;
    const int wl   = w & 7;
    const int m_w  = (wl & 1) * 16;
    const int n_w  = (wl >> 1) * 16;
    const int qr   = lane >> 2;
    const int qc   = lane & 3;
    const int b0   = (blockIdx.x & 7) * 32;
    const int u0   = (blockIdx.x >> 3) * 16;

    for (int i = t; i < 64 * 128; i += 512) {
        int r  = i >> 7;
        int kp = i & 127;
        int grow = u0 + (r & 15) + ((r >> 4) << 8);
        unsigned hi, lo;
        bsplit2(w_hh0[grow * 256 + 2 * kp], w_hh0[grow * 256 + 2 * kp + 1], hi, lo);
        W0h[r * WPK + kp] = hi;  W0l[r * WPK + kp] = lo;
        bsplit2(w_ih1[grow * 256 + 2 * kp], w_ih1[grow * 256 + 2 * kp + 1], hi, lo);
        WI1h[r * WPK + kp] = hi; WI1l[r * WPK + kp] = lo;
        bsplit2(w_hh1[grow * 256 + 2 * kp], w_hh1[grow * 256 + 2 * kp + 1], hi, lo);
        WH1h[r * WPK + kp] = hi; WH1l[r * WPK + kp] = lo;
    }
    if (t < 64) {
        int grow = u0 + (t & 15) + ((t >> 4) << 8);
#pragma unroll
        for (int k = 0; k < 7; k++) SXW[t * 8 + k] = w_ih0[grow * 7 + k];
    }

    const int eul = t & 15;
    const int er  = t >> 4;
    float bI0 = 0, bF0 = 0, bG0 = 0, bO0 = 0, bI1 = 0, bF1 = 0, bG1 = 0, bO1 = 0;
    if (t < 256) {
        int u = u0 + eul;
        bI0 = b_ih0[u]       + b_hh0[u];
        bF0 = b_ih0[u + 256] + b_hh0[u + 256];
        bG0 = b_ih0[u + 512] + b_hh0[u + 512];
        bO0 = b_ih0[u + 768] + b_hh0[u + 768];
        bI1 = b_ih1[u]       + b_hh1[u];
        bF1 = b_ih1[u + 256] + b_hh1[u + 256];
        bG1 = b_ih1[u + 512] + b_hh1[u + 512];
        bO1 = b_ih1[u + 768] + b_hh1[u + 768];
    }
    __syncthreads();

    const int gt   = t & 255;
    const int prow = gt >> 3;
    const int pc   = gt & 7;
    unsigned* CHHg = CHH + grp * 768;
    unsigned* CHLg = CHL + grp * 768;

    auto gemm_tc = [&](const float* act, const unsigned* Wh, const unsigned* Wl,
                       float (&acc)[2][4]) {
        const int kb  = grp * 128;
        const int kpb = grp * 64;
        {
            float2 p = __ldcg((const float2*)(act + (b0 + prow) * HH + kb + pc * 2));
            unsigned hi, lo; bsplit2(p.x, p.y, hi, lo);
            CHHg[prow * 12 + pc] = hi;
            CHLg[prow * 12 + pc] = lo;
        }
        __syncthreads();
        for (int ch = 0; ch < 8; ch++) {
            float2 nxt;
            const bool have = (ch + 1) < 8;
            if (have)
                nxt = __ldcg((const float2*)(act + (b0 + prow) * HH + kb + (ch + 1) * 16 + pc * 2));
            const unsigned* hbh = CHHg + (ch & 1) * 384;
            const unsigned* hbl = CHLg + (ch & 1) * 384;
            unsigned ahi[4], alo[4];
            ahi[0] = hbh[(m_w + qr) * 12 + qc];
            ahi[1] = hbh[(m_w + qr + 8) * 12 + qc];
            ahi[2] = hbh[(m_w + qr) * 12 + qc + 4];
            ahi[3] = hbh[(m_w + qr + 8) * 12 + qc + 4];
            alo[0] = hbl[(m_w + qr) * 12 + qc];
            alo[1] = hbl[(m_w + qr + 8) * 12 + qc];
            alo[2] = hbl[(m_w + qr) * 12 + qc + 4];
            alo[3] = hbl[(m_w + qr + 8) * 12 + qc + 4];
#pragma unroll
            for (int f = 0; f < 2; f++) {
                int wr  = (n_w + f * 8 + qr) * WPK + kpb + ch * 8;
                unsigned bhi[2] = {Wh[wr + qc], Wh[wr + qc + 4]};
                unsigned blo[2] = {Wl[wr + qc], Wl[wr + qc + 4]};
                MMA_BF16(acc[f], ahi, bhi);
                MMA_BF16(acc[f], ahi, blo);
                MMA_BF16(acc[f], alo, bhi);
            }
            if (have) {
                unsigned hi, lo; bsplit2(nxt.x, nxt.y, hi, lo);
                CHHg[((ch + 1) & 1) * 384 + prow * 12 + pc] = hi;
                CHLg[((ch + 1) & 1) * 384 + prow * 12 + pc] = lo;
            }
            __syncthreads();
        }
    };

    auto reduce_store = [&](float (&acc)[2][4]) {
        if (grp == 1) {
#pragma unroll
            for (int f = 0; f < 2; f++)
#pragma unroll
                for (int half = 0; half < 2; half++)
#pragma unroll
                    for (int j = 0; j < 2; j++)
                        RED[(m_w + qr + half * 8) * 68 + n_w + f * 8 + 2 * qc + j] =
                            acc[f][half * 2 + j];
        }
        __syncthreads();
        if (grp == 0) {
#pragma unroll
            for (int f = 0; f < 2; f++)
#pragma unroll
                for (int half = 0; half < 2; half++)
#pragma unroll
                    for (int j = 0; j < 2; j++)
                        RED[(m_w + qr + half * 8) * 68 + n_w + f * 8 + 2 * qc + j] +=
                            acc[f][half * 2 + j];
        }
        __syncthreads();
    };

    for (int step = 0; step < ESTEPS; step++) {
        const int pa = step & 1, pb = pa ^ 1;
        float* h0b = g_h0e[pb];
        float* h1b = g_h1e[pb];

        if (t < 32) {
            const float* xr = g_scaled + (b0 + t) * TT + step + 6;
#pragma unroll
            for (int k = 0; k < 7; k++) SXA[t * 8 + k] = xr[-k];
        }

        float acc[2][4];
#pragma unroll
        for (int f = 0; f < 2; f++)
#pragma unroll
            for (int r = 0; r < 4; r++) acc[f][r] = 0.f;

        gemm_tc(g_h0e[pa], W0h, W0l, acc);
        reduce_store(acc);

        if (t < 256) {
#pragma unroll
            for (int h2 = 0; h2 < 2; h2++) {
                int r = er + 16 * h2;
                float gi = RED[r * 68 + eul]      + bI0;
                float gf = RED[r * 68 + 16 + eul] + bF0;
                float gg = RED[r * 68 + 32 + eul] + bG0;
                float go = RED[r * 68 + 48 + eul] + bO0;
#pragma unroll
                for (int k = 0; k < 7; k++) {
                    float x = SXA[r * 8 + k];
                    gi = fmaf(x, SXW[eul * 8 + k], gi);
                    gf = fmaf(x, SXW[(16 + eul) * 8 + k], gf);
                    gg = fmaf(x, SXW[(32 + eul) * 8 + k], gg);
                    go = fmaf(x, SXW[(48 + eul) * 8 + k], go);
                }
                int idx = (b0 + r) * HH + (u0 + eul);
                float c = g_c0e[idx];
                float cn = sigf(gf) * c + sigf(gi) * tanhf(gg);
                g_c0e[idx] = cn;
                h0b[idx] = sigf(go) * tanhf(cn);
            }
        }
        __syncthreads();
        if (t == 0) { __threadfence(); atomicAdd(&g_ectr, 1u); }

#pragma unroll
        for (int f = 0; f < 2; f++)
#pragma unroll
            for (int r = 0; r < 4; r++) acc[f][r] = 0.f;

        if (t == 0) {
            unsigned tgt = 256u * (unsigned)step;
            while (*(volatile unsigned*)&g_ectr < tgt) { }
        }
        __syncthreads();
        gemm_tc(g_h1e[pa], WH1h, WH1l, acc);

        if (t == 0) {
            unsigned tgt = 256u * (unsigned)step + 128u;
            while (*(volatile unsigned*)&g_ectr < tgt) { }
        }
        __syncthreads();
        gemm_tc(h0b, WI1h, WI1l, acc);

        reduce_store(acc);

        if (t < 256) {
#pragma unroll
            for (int h2 = 0; h2 < 2; h2++) {
                int r = er + 16 * h2;
                float gi = RED[r * 68 + eul]      + bI1;
                float gf = RED[r * 68 + 16 + eul] + bF1;
                float gg = RED[r * 68 + 32 + eul] + bG1;
                float go = RED[r * 68 + 48 + eul] + bO1;
                int idx = (b0 + r) * HH + (u0 + eul);
                float c = g_c1e[idx];
                float cn = sigf(gf) * c + sigf(gi) * tanhf(gg);
                g_c1e[idx] = cn;
                h1b[idx] = sigf(go) * tanhf(cn);
            }
        }
        __syncthreads();
        if (t == 0) { __threadfence(); atomicAdd(&g_ectr, 1u); }
    }
}

// ---------------- decoder cell v6: R6 numerics, 1 sync/chunk, fused head ----------------
__global__ void __launch_bounds__(256) dec_cell_bf16(
    const float* __restrict__ xs,        // lag base (g_hist + p + 6) or null
    const float* __restrict__ w_ihs,     // (1024,7)
    const float* __restrict__ xb,        // big x (N,256) or null
    const float* __restrict__ w_ihb,     // (1024,256)
    const float* __restrict__ h_in,      // (N,256)
    const float* __restrict__ w_hh,      // (1024,256)
    const float* __restrict__ b_ih, const float* __restrict__ b_hh,
    const float* __restrict__ c_in,
    float* __restrict__ h_out, float* __restrict__ c_out,
    // layer-0 sampling prologue (p>0):
    const float* __restrict__ musig_in, const float* __restrict__ eps_prev,
    const float* __restrict__ b_mu, const float* __restrict__ b_sig, int pm1,
    // layer-1 head partials:
    const float* __restrict__ w_mu, const float* __restrict__ w_sig,
    float* __restrict__ musig_out)
{
    extern __shared__ __align__(128) char dsm[];
    unsigned* tAhi = (unsigned*)(dsm + DO_AH);
    unsigned* tAlo = (unsigned*)(dsm + DO_AL);
    unsigned* tBhi = (unsigned*)(dsm + DO_BH);
    unsigned* tBlo = (unsigned*)(dsm + DO_BL);
    float* sBias = (float*)(dsm + DO_BIAS);

    const int t    = threadIdx.x;
    const int lane = t & 31;
    const int wid  = t >> 5;
    const int m0w  = (wid & 1) * 64;
    const int u0w  = (wid >> 1) * 8;
    const int b0   = blockIdx.x * DBM;
    const int u0   = blockIdx.y * 32;

    const int lrow = t >> 1;
    const int lc0  = (t & 1) * 8;
    const int lp0  = (t & 1) * 4;
    const int lgrow = u0 + (lrow & 31) + ((lrow >> 5) << 8);

    if (t < 128) {
        int grow = u0 + (t & 31) + ((t >> 5) << 8);
        sBias[t] = b_ih[grow] + b_hh[grow];
    }

    // ---- layer-0 prologue: materialize previous step's sample into hist ----
    if (musig_in != nullptr) {
        if (t < DBM) {
            int row = b0 + t;
            float mu = musig_in[row * 2]     + b_mu[0];
            float sg = musig_in[row * 2 + 1] + b_sig[0];
            float sp = (sg > 20.f) ? sg : log1pf(expf(sg));
            g_hist[row * 32 + MAXLAG + pm1] = mu + sp * eps_prev[row];
        }
        __syncthreads();
    }

    float acc[4][4][4];
#pragma unroll
    for (int mi = 0; mi < 4; mi++)
#pragma unroll
        for (int g = 0; g < 4; g++)
#pragma unroll
            for (int r = 0; r < 4; r++) acc[mi][g][r] = 0.f;

    const int qr = lane >> 2;
    const int qc = lane & 3;

    auto compute_chunk = [&](int buf) {
        const unsigned* AH = tAhi + buf * DTILEU;
        const unsigned* AL = tAlo + buf * DTILEU;
        const unsigned* BH = tBhi + buf * DTILEU;
        const unsigned* BL = tBlo + buf * DTILEU;
        unsigned ahi[4][4], alo[4][4];
#pragma unroll
        for (int mi = 0; mi < 4; mi++) {
            int r = m0w + mi * 16 + qr;
            ahi[mi][0] = AH[r * DPK + qc];       ahi[mi][1] = AH[(r + 8) * DPK + qc];
            ahi[mi][2] = AH[r * DPK + qc + 4];   ahi[mi][3] = AH[(r + 8) * DPK + qc + 4];
            alo[mi][0] = AL[r * DPK + qc];       alo[mi][1] = AL[(r + 8) * DPK + qc];
            alo[mi][2] = AL[r * DPK + qc + 4];   alo[mi][3] = AL[(r + 8) * DPK + qc + 4];
        }
        unsigned bhi[4][2], blo[4][2];
#pragma unroll
        for (int g = 0; g < 4; g++) {
            int br = g * 32 + u0w + qr;
            bhi[g][0] = BH[br * DPK + qc]; bhi[g][1] = BH[br * DPK + qc + 4];
            blo[g][0] = BL[br * DPK + qc]; blo[g][1] = BL[br * DPK + qc + 4];
        }
#pragma unroll
        for (int mi = 0; mi < 4; mi++)
#pragma unroll
            for (int g = 0; g < 4; g++) {
                MMA_BF16(acc[mi][g], ahi[mi], bhi[g]);
                MMA_BF16(acc[mi][g], ahi[mi], blo[g]);
                MMA_BF16(acc[mi][g], alo[mi], bhi[g]);
            }
    };

    auto store_a8 = [&](int buf, const float* v) {
        unsigned hi[4], lo[4];
#pragma unroll
        for (int j = 0; j < 4; j++) bsplit2(v[2 * j], v[2 * j + 1], hi[j], lo[j]);
        *(uint4*)(tAhi + buf * DTILEU + lrow * DPK + lp0) = make_uint4(hi[0], hi[1], hi[2], hi[3]);
        *(uint4*)(tAlo + buf * DTILEU + lrow * DPK + lp0) = make_uint4(lo[0], lo[1], lo[2], lo[3]);
    };
    auto store_b8 = [&](int buf, const float* v) {
        unsigned hi[4], lo[4];
#pragma unroll
        for (int j = 0; j < 4; j++) bsplit2(v[2 * j], v[2 * j + 1], hi[j], lo[j]);
        *(uint4*)(tBhi + buf * DTILEU + lrow * DPK + lp0) = make_uint4(hi[0], hi[1], hi[2], hi[3]);
        *(uint4*)(tBlo + buf * DTILEU + lrow * DPK + lp0) = make_uint4(lo[0], lo[1], lo[2], lo[3]);
    };

    int tb = 0;

    // -------- lag chunk (K=7 zero-padded to 16) --------
    if (xs != nullptr) {
        float va[8], vb[8];
#pragma unroll
        for (int cc = 0; cc < 8; cc++) {
            int k = lc0 + cc;
            va[cc] = (k < 7) ? xs[(b0 + lrow) * 32 - k] : 0.f;
            vb[cc] = (k < 7) ? w_ihs[lgrow * 7 + k] : 0.f;
        }
        store_a8(tb, va);
        store_b8(tb, vb);
        __syncthreads();
        compute_chunk(tb);
        tb ^= 1;
    }

    // -------- dense K=256 segments: one sync per chunk --------
    auto gemm_segment = [&](const float* __restrict__ act, const float* __restrict__ wgt) {
        for (int k0 = 0; k0 < HH; k0 += 16) {
            float av[8], wv[8];
            *(float4*)(av)     = *(const float4*)(act + (long long)(b0 + lrow) * HH + k0 + lc0);
            *(float4*)(av + 4) = *(const float4*)(act + (long long)(b0 + lrow) * HH + k0 + lc0 + 4);
            *(float4*)(wv)     = *(const float4*)(wgt + (long long)lgrow * HH + k0 + lc0);
            *(float4*)(wv + 4) = *(const float4*)(wgt + (long long)lgrow * HH + k0 + lc0 + 4);
            store_a8(tb, av);
            store_b8(tb, wv);
            __syncthreads();
            compute_chunk(tb);
            tb ^= 1;
        }
    };

    if (xb != nullptr) gemm_segment(xb, w_ihb);
    gemm_segment(h_in, w_hh);

    // -------- epilogue: fused LSTM + optional head partials --------
    float wmu[2] = {0.f, 0.f}, wsg[2] = {0.f, 0.f};
    if (w_mu != nullptr) {
#pragma unroll
        for (int j = 0; j < 2; j++) {
            int u = u0 + u0w + 2 * qc + j;
            wmu[j] = w_mu[u];
            wsg[j] = w_sig[u];
        }
    }
#pragma unroll
    for (int mi = 0; mi < 4; mi++) {
        int rbase = b0 + m0w + mi * 16 + qr;
#pragma unroll
        for (int half = 0; half < 2; half++) {
            int row = rbase + half * 8;
            float hn2[2];
#pragma unroll
            for (int j = 0; j < 2; j++) {
                int ucol = 2 * qc + j;
                int u = u0 + u0w + ucol;
                int ci = half * 2 + j;
                float gi_ = acc[mi][0][ci] + sBias[ 0 + u0w + ucol];
                float gf  = acc[mi][1][ci] + sBias[32 + u0w + ucol];
                float gg  = acc[mi][2][ci] + sBias[64 + u0w + ucol];
                float go  = acc[mi][3][ci] + sBias[96 + u0w + ucol];
                long long idx = (long long)row * HH + u;
                float c = c_in[idx];
                float cn = sigf(gf) * c + sigf(gi_) * tanhf(gg);
                float hn = sigf(go) * tanhf(cn);
                c_out[idx] = cn;
                h_out[idx] = hn;
                hn2[j] = hn;
            }
            if (w_mu != nullptr) {
                float pm = hn2[0] * wmu[0] + hn2[1] * wmu[1];
                float ps = hn2[0] * wsg[0] + hn2[1] * wsg[1];
                pm += __shfl_xor_sync(0xffffffffu, pm, 1);
                ps += __shfl_xor_sync(0xffffffffu, ps, 1);
                pm += __shfl_xor_sync(0xffffffffu, pm, 2);
                ps += __shfl_xor_sync(0xffffffffu, ps, 2);
                if (qc == 0) {
                    atomicAdd(&musig_out[(long long)row * 2],     pm);
                    atomicAdd(&musig_out[(long long)row * 2 + 1], ps);
                }
            }
        }
    }
}

// ---------------- replicate encoder state x100 + init history ----------------
__global__ void replicate_kernel() {
    int row = blockIdx.x;
    int u   = threadIdx.x;
    int b   = row / SREP;
    long long d = (long long)row * HH + u;
    long long s = (long long)b * HH + u;
    g_h0d[0][d] = g_h0e[0][s];
    g_c0d[d]    = g_c0e[s];
    g_h1d[0][d] = g_h1e[0][s];
    g_c1d[d]    = g_c1e[s];
    if (u < MAXLAG) g_hist[row * 32 + u] = g_scaled[b * TT + WIN + u];
}

// ---------------- mean over samples (from musig) + denormalize ----------------
__global__ void reduce_kernel(float* __restrict__ out,
                              const float* __restrict__ eps,
                              const float* __restrict__ b_mu,
                              const float* __restrict__ b_sig) {
    int gid  = blockIdx.x * blockDim.x + threadIdx.x;
    int warp = gid >> 5;
    int lane = gid & 31;
    if (warp >= BATCH * PSTEPS) return;
    int b = warp / PSTEPS;
    int p = warp % PSTEPS;
    const float bmu = b_mu[0], bsg = b_sig[0];
    float s = 0.f;
    for (int ss = lane; ss < SREP; ss += 32) {
        long long row = (long long)b * SREP + ss;
        const float* ms = g_musig + ((long long)p * NDEC + row) * 2;
        float mu = ms[0] + bmu;
        float sg = ms[1] + bsg;
        float sp = (sg > 20.f) ? sg : log1pf(expf(sg));
        s += mu + sp * eps[(long long)p * NDEC + row];
    }
#pragma unroll
    for (int o = 16; o > 0; o >>= 1) s += __shfl_xor_sync(0xffffffffu, s, o);
    if (lane == 0)
        out[b * PSTEPS + p] = s * (1.0f / (float)SREP) * g_scale[b] + g_loc[b];
}

// ---------------- launch ----------------
extern "C" void kernel_launch(void* const* d_in, const int* in_sizes, int n_in,
                              void* d_out, int out_size) {
    const float* targets = (const float*)d_in[0];
    const float* w_ih0   = (const float*)d_in[1];
    const float* w_hh0   = (const float*)d_in[2];
    const float* b_ih0   = (const float*)d_in[3];
    const float* b_hh0   = (const float*)d_in[4];
    const float* w_ih1   = (const float*)d_in[5];
    const float* w_hh1   = (const float*)d_in[6];
    const float* b_ih1   = (const float*)d_in[7];
    const float* b_hh1   = (const float*)d_in[8];
    const float* w_mu    = (const float*)d_in[9];
    const float* b_mu    = (const float*)d_in[10];
    const float* w_sigma = (const float*)d_in[11];
    const float* b_sigma = (const float*)d_in[12];
    const float* eps     = (const float*)d_in[13];
    float* out = (float*)d_out;

    float *h0d, *c0d, *h1d, *c1d, *hist, *musig;
    cudaGetSymbolAddress((void**)&h0d, g_h0d);
    cudaGetSymbolAddress((void**)&c0d, g_c0d);
    cudaGetSymbolAddress((void**)&h1d, g_h1d);
    cudaGetSymbolAddress((void**)&c1d, g_c1d);
    cudaGetSymbolAddress((void**)&hist, g_hist);
    cudaGetSymbolAddress((void**)&musig, g_musig);

    cudaFuncSetAttribute(encoder_kernel,
                         cudaFuncAttributeMaxDynamicSharedMemorySize, ENC_SMEM_BYTES);
    cudaFuncSetAttribute(dec_cell_bf16,
                         cudaFuncAttributeMaxDynamicSharedMemorySize, DEC_SMEM_BYTES);

    norm_kernel<<<BATCH, 256>>>(targets);
    zero_enc_kernel<<<(BATCH * HH + 255) / 256, 256>>>();
    zero_musig_kernel<<<1024, 256>>>();

    encoder_kernel<<<ENC_BLOCKS, 512, ENC_SMEM_BYTES>>>(
        w_ih0, w_hh0, b_ih0, b_hh0, w_ih1, w_hh1, b_ih1, b_hh1);

    replicate_kernel<<<NDEC, 256>>>();

    for (int p = 0; p < PSTEPS; p++) {
        int pa = p & 1, pb = pa ^ 1;
        const float* ms_in = (p > 0) ? (musig + (long long)(p - 1) * NDEC * 2) : nullptr;
        const float* ep    = (p > 0) ? (eps + (long long)(p - 1) * NDEC) : nullptr;
        // layer 0: sample prev step + lags + h0 @ w_hh0^T
        dec_cell_bf16<<<dim3(NDEC / DBM, 8), 256, DEC_SMEM_BYTES>>>(
            hist + p + 6, w_ih0,
            nullptr, nullptr,
            h0d + pa * (NDEC * HH), w_hh0, b_ih0, b_hh0,
            c0d, h0d + pb * (NDEC * HH), c0d,
            ms_in, ep, b_mu, b_sigma, p - 1,
            nullptr, nullptr, nullptr);
        // layer 1: h0_new @ w_ih1^T + h1 @ w_hh1^T, fused head partials
        dec_cell_bf16<<<dim3(NDEC / DBM, 8), 256, DEC_SMEM_BYTES>>>(
            nullptr, nullptr,
            h0d + pb * (NDEC * HH), w_ih1,
            h1d + pa * (NDEC * HH), w_hh1, b_ih1, b_hh1,
            c1d, h1d + pb * (NDEC * HH), c1d,
            nullptr, nullptr, nullptr, nullptr, 0,
            w_mu, w_sigma, musig + (long long)p * NDEC * 2);
    }

    reduce_kernel<<<(BATCH * PSTEPS * 32 + 255) / 256, 256>>>(out, eps, b_mu, b_sigma);
}